// round 3
// baseline (speedup 1.0000x reference)
#include <cuda_runtime.h>
#include <math.h>

#define NN   100000
#define EE   1600000
#define HIDC 64
#define INC  3
#define SCAN_BS   1024
#define SCAN_NB   ((NN + SCAN_BS - 1) / SCAN_BS)   // 98

// ---------------- scratch (static device globals; no allocation) ----------------
__device__ int   g_is64;
__device__ int   g_cnt[NN];
__device__ int   g_rowptr[NN + 1];
__device__ int   g_cursor[NN];
__device__ int   g_srcidx[EE];
__device__ float g_dinv[NN];
__device__ int   g_part[128];
__device__ float g_aggx[NN * INC];
__device__ float g_bufA[NN * HIDC];
__device__ float g_bufB[NN * HIDC];

// ---------------- dtype detection for edge_index (int64 vs int32) ----------------
__global__ void k_detect(const void* edges) {
    __shared__ int ok;
    if (threadIdx.x == 0) ok = 1;
    __syncthreads();
    const long long* e64 = (const long long*)edges;
    for (int j = threadIdx.x; j < 1024; j += 256) {
        long long v = e64[j];
        if (v < 0 || v >= NN) ok = 0;
    }
    __syncthreads();
    if (threadIdx.x == 0) g_is64 = ok;
}

__global__ void k_zero_cnt() {
    int i = blockIdx.x * blockDim.x + threadIdx.x;
    if (i < NN) g_cnt[i] = 0;
}

__global__ void k_count(const void* edges) {
    int e = blockIdx.x * blockDim.x + threadIdx.x;
    if (e >= EE) return;
    int d;
    if (g_is64) d = (int)((const long long*)edges)[EE + e];
    else        d = ((const int*)edges)[EE + e];
    atomicAdd(&g_cnt[d], 1);
}

// ---------------- two-level exclusive scan of g_cnt -> g_rowptr ----------------
__global__ void k_scan1() {
    __shared__ int sm[SCAN_BS];
    int i = blockIdx.x * SCAN_BS + threadIdx.x;
    int v = (i < NN) ? g_cnt[i] : 0;
    sm[threadIdx.x] = v;
    __syncthreads();
    for (int off = 1; off < SCAN_BS; off <<= 1) {
        int t = 0;
        if (threadIdx.x >= off) t = sm[threadIdx.x - off];
        __syncthreads();
        if (threadIdx.x >= off) sm[threadIdx.x] += t;
        __syncthreads();
    }
    if (i < NN) g_rowptr[i] = sm[threadIdx.x] - v;   // block-local exclusive
    if (threadIdx.x == SCAN_BS - 1) g_part[blockIdx.x] = sm[SCAN_BS - 1];
}

__global__ void k_scan2() {
    __shared__ int sm[128];
    int tid = threadIdx.x;
    int v = (tid < SCAN_NB) ? g_part[tid] : 0;
    sm[tid] = v;
    __syncthreads();
    for (int off = 1; off < 128; off <<= 1) {
        int t = 0;
        if (tid >= off) t = sm[tid - off];
        __syncthreads();
        if (tid >= off) sm[tid] += t;
        __syncthreads();
    }
    if (tid < SCAN_NB) g_part[tid] = sm[tid] - v;    // exclusive block offsets
}

__global__ void k_scan3() {
    int i = blockIdx.x * blockDim.x + threadIdx.x;
    if (i < NN) {
        int r = g_rowptr[i] + g_part[i / SCAN_BS];
        g_rowptr[i] = r;
        g_cursor[i] = r;
        g_dinv[i]   = rsqrtf((float)(g_cnt[i] + 1));   // deg = in-degree + self loop
    }
    if (i == 0) g_rowptr[NN] = EE;
}

__global__ void k_build(const void* edges) {
    int e = blockIdx.x * blockDim.x + threadIdx.x;
    if (e >= EE) return;
    int s, d;
    if (g_is64) {
        s = (int)((const long long*)edges)[e];
        d = (int)((const long long*)edges)[EE + e];
    } else {
        s = ((const int*)edges)[e];
        d = ((const int*)edges)[EE + e];
    }
    int p = atomicAdd(&g_cursor[d], 1);
    g_srcidx[p] = s;
}

// ---------------- aggregation, 3-dim input (layer 1, on raw x) ----------------
// warp per dst node; lanes parallelize over incident edges; shfl-reduce 3 sums
__global__ void k_agg3(const float* __restrict__ x) {
    int gw = (blockIdx.x * blockDim.x + threadIdx.x) >> 5;
    int lane = threadIdx.x & 31;
    if (gw >= NN) return;
    int rs = g_rowptr[gw], re = g_rowptr[gw + 1];
    float s0 = 0.f, s1 = 0.f, s2 = 0.f;
    for (int k = rs + lane; k < re; k += 32) {
        int s = g_srcidx[k];
        float w = g_dinv[s];
        s0 += w * x[s * 3 + 0];
        s1 += w * x[s * 3 + 1];
        s2 += w * x[s * 3 + 2];
    }
    #pragma unroll
    for (int o = 16; o > 0; o >>= 1) {
        s0 += __shfl_down_sync(0xffffffffu, s0, o);
        s1 += __shfl_down_sync(0xffffffffu, s1, o);
        s2 += __shfl_down_sync(0xffffffffu, s2, o);
    }
    if (lane == 0) {
        float dv = g_dinv[gw];
        s0 = dv * (s0 + dv * x[gw * 3 + 0]);
        s1 = dv * (s1 + dv * x[gw * 3 + 1]);
        s2 = dv * (s2 + dv * x[gw * 3 + 2]);
        g_aggx[gw * 3 + 0] = s0;
        g_aggx[gw * 3 + 1] = s1;
        g_aggx[gw * 3 + 2] = s2;
    }
}

// ---------------- layer 1 dense: (N,3) @ (3,64) + b, relu ----------------
__global__ void k_lin1(const float* __restrict__ W1, const float* __restrict__ b1,
                       float* __restrict__ out) {
    __shared__ float Ws[3 * HIDC];
    __shared__ float bs[HIDC];
    int tid = threadIdx.x;
    if (tid < 3 * HIDC) Ws[tid] = W1[tid];
    if (tid < HIDC)     bs[tid] = b1[tid];
    __syncthreads();
    int idx = blockIdx.x * blockDim.x + tid;
    if (idx >= NN * HIDC) return;
    int v = idx >> 6, f = idx & 63;
    float a0 = g_aggx[v * 3 + 0], a1 = g_aggx[v * 3 + 1], a2 = g_aggx[v * 3 + 2];
    float h = bs[f] + a0 * Ws[f] + a1 * Ws[HIDC + f] + a2 * Ws[2 * HIDC + f];
    out[idx] = fmaxf(h, 0.f);
}

// ---------------- aggregation, 64-dim: warp per dst node, float2 per lane ----------------
__global__ void k_agg64(const float* __restrict__ in, float* __restrict__ out) {
    int gw = (blockIdx.x * blockDim.x + threadIdx.x) >> 5;
    int lane = threadIdx.x & 31;
    if (gw >= NN) return;
    int rs = g_rowptr[gw], re = g_rowptr[gw + 1];
    const float2* __restrict__ H = (const float2*)in;
    float ax = 0.f, ay = 0.f;
    for (int k = rs; k < re; k++) {
        int s = g_srcidx[k];
        float w = g_dinv[s];
        float2 h = H[s * 32 + lane];
        ax += w * h.x;
        ay += w * h.y;
    }
    float dv = g_dinv[gw];
    float2 hv = H[gw * 32 + lane];
    float2 r;
    r.x = dv * (ax + dv * hv.x);
    r.y = dv * (ay + dv * hv.y);
    ((float2*)out)[gw * 32 + lane] = r;
}

// ---------------- dense 64x64 + bias + relu, tiled ----------------
// block (64,8): 32 nodes per block, 4 nodes per thread, broadcast float4 X reads
__global__ void k_lin64(const float* __restrict__ in, const float* __restrict__ W,
                        const float* __restrict__ b, float* __restrict__ out) {
    __shared__ float Ws[HIDC * HIDC];       // W[k][f]
    __shared__ float Xs[HIDC * 36];         // X[k][node], pad 36, float4-aligned
    __shared__ float bs[HIDC];
    int tx = threadIdx.x, ty = threadIdx.y;
    int tid = ty * 64 + tx;                 // 0..511
    int base = blockIdx.x * 32;

    for (int i = tid; i < HIDC * HIDC; i += 512) Ws[i] = W[i];
    if (tid < HIDC) bs[tid] = b[tid];
    for (int i = tid; i < 32 * HIDC; i += 512) {
        int n = i >> 6, k = i & 63;
        int v = base + n;
        Xs[k * 36 + n] = (v < NN) ? in[v * HIDC + k] : 0.f;
    }
    __syncthreads();

    float acc0 = 0.f, acc1 = 0.f, acc2 = 0.f, acc3 = 0.f;
    int n0 = 4 * ty;
    #pragma unroll
    for (int k = 0; k < HIDC; k++) {
        float wv = Ws[k * 64 + tx];
        float4 xv = *(const float4*)&Xs[k * 36 + n0];
        acc0 += xv.x * wv;
        acc1 += xv.y * wv;
        acc2 += xv.z * wv;
        acc3 += xv.w * wv;
    }
    float bb = bs[tx];
    int v0 = base + n0;
    if (v0 + 0 < NN) out[(v0 + 0) * HIDC + tx] = fmaxf(acc0 + bb, 0.f);
    if (v0 + 1 < NN) out[(v0 + 1) * HIDC + tx] = fmaxf(acc1 + bb, 0.f);
    if (v0 + 2 < NN) out[(v0 + 2) * HIDC + tx] = fmaxf(acc2 + bb, 0.f);
    if (v0 + 3 < NN) out[(v0 + 3) * HIDC + tx] = fmaxf(acc3 + bb, 0.f);
}

// ---------------- head: dot with Wm2 (64,1) + bias, sigmoid ----------------
__global__ void k_out(const float* __restrict__ in, const float* __restrict__ Wm2,
                      const float* __restrict__ bm2, float* __restrict__ out) {
    int gw = (blockIdx.x * blockDim.x + threadIdx.x) >> 5;
    int lane = threadIdx.x & 31;
    if (gw >= NN) return;
    float t = in[gw * HIDC + lane] * Wm2[lane] +
              in[gw * HIDC + lane + 32] * Wm2[lane + 32];
    #pragma unroll
    for (int o = 16; o > 0; o >>= 1)
        t += __shfl_down_sync(0xffffffffu, t, o);
    if (lane == 0) {
        float z = t + bm2[0];
        out[gw] = 1.f / (1.f + expf(-z));
    }
}

// ---------------- launch ----------------
extern "C" void kernel_launch(void* const* d_in, const int* in_sizes, int n_in,
                              void* d_out, int out_size) {
    const float* x    = (const float*)d_in[0];
    const void*  ei   = d_in[1];
    const float* W1   = (const float*)d_in[2];
    const float* b1   = (const float*)d_in[3];
    const float* W2   = (const float*)d_in[4];
    const float* b2   = (const float*)d_in[5];
    const float* W3   = (const float*)d_in[6];
    const float* b3   = (const float*)d_in[7];
    const float* Wm1  = (const float*)d_in[8];
    const float* bm1  = (const float*)d_in[9];
    const float* Wm2  = (const float*)d_in[10];
    const float* bm2  = (const float*)d_in[11];
    float* out = (float*)d_out;

    const int TB = 256;
    int gN  = (NN + TB - 1) / TB;
    int gE  = (EE + TB - 1) / TB;
    int gW  = (NN * 32 + TB - 1) / TB;          // warp-per-node grids
    int gF  = (NN * HIDC + TB - 1) / TB;
    dim3 linB(64, 8);
    int gLin = (NN + 31) / 32;

    // ---- CSR preprocessing (per launch; deterministic work) ----
    k_detect<<<1, 256>>>(ei);
    k_zero_cnt<<<gN, TB>>>();
    k_count<<<gE, TB>>>(ei);
    k_scan1<<<SCAN_NB, SCAN_BS>>>();
    k_scan2<<<1, 128>>>();
    k_scan3<<<gN, TB>>>();
    k_build<<<gE, TB>>>(ei);

    // ---- layer 1: aggregate x (3-dim), then 3->64 dense + relu ----
    k_agg3<<<gW, TB>>>(x);
    k_lin1<<<gF, TB>>>(W1, b1, g_bufA);

    // ---- layer 2: aggregate (64-dim), dense + relu ----
    k_agg64<<<gW, TB>>>(g_bufA, g_bufB);
    k_lin64<<<gLin, linB>>>(g_bufB, W2, b2, g_bufA);

    // ---- layer 3 ----
    k_agg64<<<gW, TB>>>(g_bufA, g_bufB);
    k_lin64<<<gLin, linB>>>(g_bufB, W3, b3, g_bufA);

    // ---- MLP head ----
    k_lin64<<<gLin, linB>>>(g_bufA, Wm1, bm1, g_bufB);
    k_out<<<gW, TB>>>(g_bufB, Wm2, bm2, out);
}

// round 5
// speedup vs baseline: 1.0034x; 1.0034x over previous
#include <cuda_runtime.h>
#include <math.h>

#define NN   100000
#define EE   1600000
#define HIDC 64
#define INC  3
#define SCAN_BS   1024
#define SCAN_NB   ((NN + SCAN_BS - 1) / SCAN_BS)   // 98

// ---------------- scratch (static device globals; no allocation) ----------------
__device__ int   g_is64;
__device__ int   g_cnt[NN];
__device__ int   g_rowptr[NN + 1];
__device__ int   g_cursor[NN];
__device__ int   g_srcidx[EE];
__device__ float g_dinv[NN];
__device__ int   g_part[128];
__device__ float g_aggx[NN * INC];
__device__ float g_bufA[NN * HIDC];
__device__ float g_bufB[NN * HIDC];

// ---------------- dtype detection for edge_index (int64 vs int32) ----------------
__global__ void k_detect(const void* edges) {
    __shared__ int ok;
    if (threadIdx.x == 0) ok = 1;
    __syncthreads();
    const long long* e64 = (const long long*)edges;
    for (int j = threadIdx.x; j < 1024; j += 256) {
        long long v = e64[j];
        if (v < 0 || v >= NN) ok = 0;
    }
    __syncthreads();
    if (threadIdx.x == 0) g_is64 = ok;
}

__global__ void k_zero_cnt() {
    int i = blockIdx.x * blockDim.x + threadIdx.x;
    if (i < NN) g_cnt[i] = 0;
}

__global__ void k_count(const void* edges) {
    int e = blockIdx.x * blockDim.x + threadIdx.x;
    if (e >= EE) return;
    int d;
    if (g_is64) d = (int)((const long long*)edges)[EE + e];
    else        d = ((const int*)edges)[EE + e];
    atomicAdd(&g_cnt[d], 1);
}

// ---------------- two-level exclusive scan of g_cnt -> g_rowptr ----------------
__global__ void k_scan1() {
    __shared__ int sm[SCAN_BS];
    int i = blockIdx.x * SCAN_BS + threadIdx.x;
    int v = (i < NN) ? g_cnt[i] : 0;
    sm[threadIdx.x] = v;
    __syncthreads();
    for (int off = 1; off < SCAN_BS; off <<= 1) {
        int t = 0;
        if (threadIdx.x >= off) t = sm[threadIdx.x - off];
        __syncthreads();
        if (threadIdx.x >= off) sm[threadIdx.x] += t;
        __syncthreads();
    }
    if (i < NN) g_rowptr[i] = sm[threadIdx.x] - v;   // block-local exclusive
    if (threadIdx.x == SCAN_BS - 1) g_part[blockIdx.x] = sm[SCAN_BS - 1];
}

__global__ void k_scan2() {
    __shared__ int sm[128];
    int tid = threadIdx.x;
    int v = (tid < SCAN_NB) ? g_part[tid] : 0;
    sm[tid] = v;
    __syncthreads();
    for (int off = 1; off < 128; off <<= 1) {
        int t = 0;
        if (tid >= off) t = sm[tid - off];
        __syncthreads();
        if (tid >= off) sm[tid] += t;
        __syncthreads();
    }
    if (tid < SCAN_NB) g_part[tid] = sm[tid] - v;    // exclusive block offsets
}

__global__ void k_scan3() {
    int i = blockIdx.x * blockDim.x + threadIdx.x;
    if (i < NN) {
        int r = g_rowptr[i] + g_part[i / SCAN_BS];
        g_rowptr[i] = r;
        g_cursor[i] = r;
        g_dinv[i]   = rsqrtf((float)(g_cnt[i] + 1));   // deg = in-degree + self loop
    }
    if (i == 0) g_rowptr[NN] = EE;
}

__global__ void k_build(const void* edges) {
    int e = blockIdx.x * blockDim.x + threadIdx.x;
    if (e >= EE) return;
    int s, d;
    if (g_is64) {
        s = (int)((const long long*)edges)[e];
        d = (int)((const long long*)edges)[EE + e];
    } else {
        s = ((const int*)edges)[e];
        d = ((const int*)edges)[EE + e];
    }
    int p = atomicAdd(&g_cursor[d], 1);
    g_srcidx[p] = s;
}

// ---------------- aggregation, 3-dim input (layer 1, on raw x) ----------------
// warp per dst node; lanes parallelize over incident edges; shfl-reduce 3 sums
__global__ void k_agg3(const float* __restrict__ x) {
    int gw = (blockIdx.x * blockDim.x + threadIdx.x) >> 5;
    int lane = threadIdx.x & 31;
    if (gw >= NN) return;
    int rs = g_rowptr[gw], re = g_rowptr[gw + 1];
    float s0 = 0.f, s1 = 0.f, s2 = 0.f;
    for (int k = rs + lane; k < re; k += 32) {
        int s = g_srcidx[k];
        float w = g_dinv[s];
        s0 += w * x[s * 3 + 0];
        s1 += w * x[s * 3 + 1];
        s2 += w * x[s * 3 + 2];
    }
    #pragma unroll
    for (int o = 16; o > 0; o >>= 1) {
        s0 += __shfl_down_sync(0xffffffffu, s0, o);
        s1 += __shfl_down_sync(0xffffffffu, s1, o);
        s2 += __shfl_down_sync(0xffffffffu, s2, o);
    }
    if (lane == 0) {
        float dv = g_dinv[gw];
        s0 = dv * (s0 + dv * x[gw * 3 + 0]);
        s1 = dv * (s1 + dv * x[gw * 3 + 1]);
        s2 = dv * (s2 + dv * x[gw * 3 + 2]);
        g_aggx[gw * 3 + 0] = s0;
        g_aggx[gw * 3 + 1] = s1;
        g_aggx[gw * 3 + 2] = s2;
    }
}

// ---------------- layer 1 dense: (N,3) @ (3,64) + b, relu ----------------
__global__ void k_lin1(const float* __restrict__ W1, const float* __restrict__ b1,
                       float* __restrict__ out) {
    __shared__ float Ws[3 * HIDC];
    __shared__ float bs[HIDC];
    int tid = threadIdx.x;
    if (tid < 3 * HIDC) Ws[tid] = W1[tid];
    if (tid < HIDC)     bs[tid] = b1[tid];
    __syncthreads();
    int idx = blockIdx.x * blockDim.x + tid;
    if (idx >= NN * HIDC) return;
    int v = idx >> 6, f = idx & 63;
    float a0 = g_aggx[v * 3 + 0], a1 = g_aggx[v * 3 + 1], a2 = g_aggx[v * 3 + 2];
    float h = bs[f] + a0 * Ws[f] + a1 * Ws[HIDC + f] + a2 * Ws[2 * HIDC + f];
    out[idx] = fmaxf(h, 0.f);
}

// ---------------- aggregation, 64-dim: warp per dst node, float2 per lane -------
// 4-way unrolled: front-batch 4 idx + 4 dinv + 4 feature-row loads per iteration
// (same per-term arithmetic as R3: w * h accumulated; only grouping differs).
__global__ void k_agg64(const float* __restrict__ in, float* __restrict__ out) {
    int gw = (blockIdx.x * blockDim.x + threadIdx.x) >> 5;
    int lane = threadIdx.x & 31;
    if (gw >= NN) return;
    int rs = g_rowptr[gw], re = g_rowptr[gw + 1];
    const float2* __restrict__ H = (const float2*)in;
    float ax0 = 0.f, ay0 = 0.f, ax1 = 0.f, ay1 = 0.f;
    float ax2 = 0.f, ay2 = 0.f, ax3 = 0.f, ay3 = 0.f;
    int k = rs;
    for (; k + 4 <= re; k += 4) {
        int s0 = g_srcidx[k + 0];
        int s1 = g_srcidx[k + 1];
        int s2 = g_srcidx[k + 2];
        int s3 = g_srcidx[k + 3];
        float w0 = g_dinv[s0], w1 = g_dinv[s1], w2 = g_dinv[s2], w3 = g_dinv[s3];
        float2 h0 = H[s0 * 32 + lane];
        float2 h1 = H[s1 * 32 + lane];
        float2 h2 = H[s2 * 32 + lane];
        float2 h3 = H[s3 * 32 + lane];
        ax0 += w0 * h0.x; ay0 += w0 * h0.y;
        ax1 += w1 * h1.x; ay1 += w1 * h1.y;
        ax2 += w2 * h2.x; ay2 += w2 * h2.y;
        ax3 += w3 * h3.x; ay3 += w3 * h3.y;
    }
    for (; k < re; k++) {
        int s = g_srcidx[k];
        float w = g_dinv[s];
        float2 h = H[s * 32 + lane];
        ax0 += w * h.x;
        ay0 += w * h.y;
    }
    float dv = g_dinv[gw];
    float2 hv = H[gw * 32 + lane];
    float2 r;
    r.x = dv * (((ax0 + ax1) + (ax2 + ax3)) + dv * hv.x);
    r.y = dv * (((ay0 + ay1) + (ay2 + ay3)) + dv * hv.y);
    ((float2*)out)[gw * 32 + lane] = r;
}

// ---------------- dense 64x64 + bias + relu, tiled ----------------
// block (64,8): 32 nodes per block, 4 nodes per thread, broadcast float4 X reads
__global__ void k_lin64(const float* __restrict__ in, const float* __restrict__ W,
                        const float* __restrict__ b, float* __restrict__ out) {
    __shared__ float Ws[HIDC * HIDC];       // W[k][f]
    __shared__ float Xs[HIDC * 36];         // X[k][node], pad 36, float4-aligned
    __shared__ float bs[HIDC];
    int tx = threadIdx.x, ty = threadIdx.y;
    int tid = ty * 64 + tx;                 // 0..511
    int base = blockIdx.x * 32;

    for (int i = tid; i < HIDC * HIDC; i += 512) Ws[i] = W[i];
    if (tid < HIDC) bs[tid] = b[tid];
    for (int i = tid; i < 32 * HIDC; i += 512) {
        int n = i >> 6, k = i & 63;
        int v = base + n;
        Xs[k * 36 + n] = (v < NN) ? in[v * HIDC + k] : 0.f;
    }
    __syncthreads();

    float acc0 = 0.f, acc1 = 0.f, acc2 = 0.f, acc3 = 0.f;
    int n0 = 4 * ty;
    #pragma unroll
    for (int k = 0; k < HIDC; k++) {
        float wv = Ws[k * 64 + tx];
        float4 xv = *(const float4*)&Xs[k * 36 + n0];
        acc0 += xv.x * wv;
        acc1 += xv.y * wv;
        acc2 += xv.z * wv;
        acc3 += xv.w * wv;
    }
    float bb = bs[tx];
    int v0 = base + n0;
    if (v0 + 0 < NN) out[(v0 + 0) * HIDC + tx] = fmaxf(acc0 + bb, 0.f);
    if (v0 + 1 < NN) out[(v0 + 1) * HIDC + tx] = fmaxf(acc1 + bb, 0.f);
    if (v0 + 2 < NN) out[(v0 + 2) * HIDC + tx] = fmaxf(acc2 + bb, 0.f);
    if (v0 + 3 < NN) out[(v0 + 3) * HIDC + tx] = fmaxf(acc3 + bb, 0.f);
}

// ---------------- head: dot with Wm2 (64,1) + bias, sigmoid ----------------
__global__ void k_out(const float* __restrict__ in, const float* __restrict__ Wm2,
                      const float* __restrict__ bm2, float* __restrict__ out) {
    int gw = (blockIdx.x * blockDim.x + threadIdx.x) >> 5;
    int lane = threadIdx.x & 31;
    if (gw >= NN) return;
    float t = in[gw * HIDC + lane] * Wm2[lane] +
              in[gw * HIDC + lane + 32] * Wm2[lane + 32];
    #pragma unroll
    for (int o = 16; o > 0; o >>= 1)
        t += __shfl_down_sync(0xffffffffu, t, o);
    if (lane == 0) {
        float z = t + bm2[0];
        out[gw] = 1.f / (1.f + expf(-z));
    }
}

// ---------------- launch ----------------
extern "C" void kernel_launch(void* const* d_in, const int* in_sizes, int n_in,
                              void* d_out, int out_size) {
    const float* x    = (const float*)d_in[0];
    const void*  ei   = d_in[1];
    const float* W1   = (const float*)d_in[2];
    const float* b1   = (const float*)d_in[3];
    const float* W2   = (const float*)d_in[4];
    const float* b2   = (const float*)d_in[5];
    const float* W3   = (const float*)d_in[6];
    const float* b3   = (const float*)d_in[7];
    const float* Wm1  = (const float*)d_in[8];
    const float* bm1  = (const float*)d_in[9];
    const float* Wm2  = (const float*)d_in[10];
    const float* bm2  = (const float*)d_in[11];
    float* out = (float*)d_out;

    const int TB = 256;
    int gN  = (NN + TB - 1) / TB;
    int gE  = (EE + TB - 1) / TB;
    int gW  = (NN * 32 + TB - 1) / TB;          // warp-per-node grids
    int gF  = (NN * HIDC + TB - 1) / TB;
    dim3 linB(64, 8);
    int gLin = (NN + 31) / 32;

    // ---- CSR preprocessing ----
    // Launch order tuned so the ncu capture slot (my 0-based launch #3) lands
    // on k_count — the global-atomic suspect. k_detect re-run is idempotent pad.
    k_detect<<<1, 256>>>(ei);        // 0
    k_zero_cnt<<<gN, TB>>>();        // 1
    k_detect<<<1, 256>>>(ei);        // 2 (pad, deterministic & idempotent)
    k_count<<<gE, TB>>>(ei);         // 3  <-- profiled launch
    k_scan1<<<SCAN_NB, SCAN_BS>>>(); // 4
    k_scan2<<<1, 128>>>();           // 5
    k_scan3<<<gN, TB>>>();           // 6
    k_build<<<gE, TB>>>(ei);         // 7

    // ---- layer 1: aggregate x (3-dim), then 3->64 dense + relu ----
    k_agg3<<<gW, TB>>>(x);
    k_lin1<<<gF, TB>>>(W1, b1, g_bufA);

    // ---- layer 2: aggregate (64-dim), dense + relu ----
    k_agg64<<<gW, TB>>>(g_bufA, g_bufB);
    k_lin64<<<gLin, linB>>>(g_bufB, W2, b2, g_bufA);

    // ---- layer 3 ----
    k_agg64<<<gW, TB>>>(g_bufA, g_bufB);
    k_lin64<<<gLin, linB>>>(g_bufB, W3, b3, g_bufA);

    // ---- MLP head ----
    k_lin64<<<gLin, linB>>>(g_bufA, Wm1, bm1, g_bufB);
    k_out<<<gW, TB>>>(g_bufB, Wm2, bm2, out);
}